// round 1
// baseline (speedup 1.0000x reference)
#include <cuda_runtime.h>

#define BATCHN 256
#define SEQN   1024
#define HIDN   200
#define VOCABN 33

#define NCP   100   // column pairs (200 cols / 2)
#define NCHK  5     // i-range chunks
#define NI    40    // i per chunk (NCHK*NI = 200)
#define NWRK  (NCP*NCHK)  // 500 worker threads
#define TPB   512

// Device-global scratch (allocation-free rule: __device__ arrays are the
// sanctioned scratch mechanism).
__device__ float d_E2[VOCABN * HIDN];
__device__ int   d_x_is32;

// ---------------------------------------------------------------------------
// Kernel 1: E2[v][j] = sum_e embedding[v][e] * W_e[e][j]   (33 x 200)
// Also: detect whether x arrived as int32 (jax x64-demotion) or int64.
// For int64 nonneg values < 33, every odd 32-bit word is 0; for a random
// int32 array in [0,33) the chance all 128 sampled odd words are 0 is ~33^-64.
// ---------------------------------------------------------------------------
__global__ void prep_kernel(const float* __restrict__ emb,
                            const float* __restrict__ We,
                            const int* __restrict__ x32) {
    int v = blockIdx.x, j = threadIdx.x;
    if (v == 0 && j == 0) {
        int is32 = 0;
        for (int i = 0; i < 128; i++)
            if (x32[2 * i + 1] != 0) is32 = 1;
        d_x_is32 = is32;
    }
    float acc = 0.f;
#pragma unroll 8
    for (int e = 0; e < HIDN; e++)
        acc += emb[v * HIDN + e] * We[e * HIDN + j];
    d_E2[v * HIDN + j] = acc;
}

// ---------------------------------------------------------------------------
// Scan kernel: 128 CTAs x 2 batch rows, W_h register-resident,
// fma.rn.f32x2 packed fp32 math, logits fused one step behind.
// ---------------------------------------------------------------------------
struct Smem {
    float4 hdup[HIDN];              // {h_row0, h_row0, h_row1, h_row1} per col
    float  e2[VOCABN * HIDN];       // gathered input-projection table
    float  wo[HIDN * VOCABN];       // W_o
    float2 part[NCHK][2][NCP];      // GEMV partials [chunk][row][colpair]
    float  lp[NCHK][2][VOCABN];     // logits partials
    int    xi[2][SEQN];             // token ids for this CTA's two rows
};

union F2U { unsigned long long u; float2 f2; };

__device__ __forceinline__ void fma2(unsigned long long& d,
                                     unsigned long long a,
                                     unsigned long long b) {
    asm("fma.rn.f32x2 %0, %1, %2, %0;" : "+l"(d) : "l"(a), "l"(b));
}

extern __shared__ unsigned char smem_raw[];

__global__ void __launch_bounds__(TPB, 1)
scan_kernel(const void* __restrict__ xv,
            const float* __restrict__ hidden,
            const float* __restrict__ Wh,
            const float* __restrict__ Wo,
            float* __restrict__ out_logits,
            float* __restrict__ out_hidden,
            int write_h) {
    Smem& s = *reinterpret_cast<Smem*>(smem_raw);
    const int tid = threadIdx.x;
    const int b0  = blockIdx.x * 2;

    // ---- cooperative setup loads ----
    for (int k = tid; k < VOCABN * HIDN; k += TPB) s.e2[k] = d_E2[k];
    for (int k = tid; k < HIDN * VOCABN; k += TPB) s.wo[k] = Wo[k];
    {
        const int is32 = d_x_is32;
        const int* __restrict__ x32 = (const int*)xv;
        const long long* __restrict__ x64 = (const long long*)xv;
        for (int k = tid; k < 2 * SEQN; k += TPB) {
            int r = k >> 10, t = k & (SEQN - 1);
            long long idx = is32 ? (long long)x32[(size_t)(b0 + r) * SEQN + t]
                                 : x64[(size_t)(b0 + r) * SEQN + t];
            s.xi[r][t] = (int)idx;
        }
    }
    for (int j = tid; j < HIDN; j += TPB) {
        float a = hidden[(size_t)b0 * HIDN + j];
        float b = hidden[(size_t)(b0 + 1) * HIDN + j];
        s.hdup[j] = make_float4(a, a, b, b);
    }

    // ---- W_h column-pair slice into registers ----
    const int cp = tid % NCP;     // column pair: cols 2cp, 2cp+1
    const int ch = tid / NCP;     // i-chunk 0..4 (5 == idle)
    unsigned long long wreg[NI];
    if (tid < NWRK) {
        const float* wp = Wh + (size_t)(ch * NI) * HIDN + 2 * cp;
#pragma unroll
        for (int ii = 0; ii < NI; ii++)
            wreg[ii] = *reinterpret_cast<const unsigned long long*>(wp + (size_t)ii * HIDN);
    }

    // logits task mapping (threads 0..329): (vocab, row, chunk)
    const int lv  = tid % VOCABN;
    const int lrc = tid / VOCABN;
    const int lrow = lrc & 1;
    const int lch  = lrc >> 1;

    __syncthreads();

    // ---- main scan: iteration t does GEMV for step t (t<SEQ) and logits
    //      for step t-1 (t>0), both reading h_{t-1} currently in s.hdup ----
    for (int t = 0; t <= SEQN; t++) {
        // Phase 1a: recurrent GEMV partials (packed f32x2)
        if (tid < NWRK && t < SEQN) {
            F2U a0, a1;
            a0.u = 0ull; a1.u = 0ull;
            const float4* hp = &s.hdup[ch * NI];
#pragma unroll
            for (int ii = 0; ii < NI; ii++) {
                ulonglong2 hd = *reinterpret_cast<const ulonglong2*>(hp + ii);
                fma2(a0.u, wreg[ii], hd.x);   // row 0
                fma2(a1.u, wreg[ii], hd.y);   // row 1
            }
            s.part[ch][0][cp] = a0.f2;
            s.part[ch][1][cp] = a1.f2;
        }
        // Phase 1b: logits partials for step t-1 (same h)
        if (tid < 2 * NCHK * VOCABN && t > 0) {
            const float* hb = reinterpret_cast<const float*>(s.hdup) + lrow * 2;
            float lacc0 = 0.f, lacc1 = 0.f;
#pragma unroll 8
            for (int ii = 0; ii < NI; ii += 2) {
                int i = lch * NI + ii;
                lacc0 += hb[(size_t)i * 4]       * s.wo[i * VOCABN + lv];
                lacc1 += hb[(size_t)(i + 1) * 4] * s.wo[(i + 1) * VOCABN + lv];
            }
            s.lp[lch][lrow][lv] = lacc0 + lacc1;
        }
        __syncthreads();

        // Phase 2a: finalize h_t (threads 0..199)
        if (tid < 2 * NCP && t < SEQN) {
            const int fcp  = tid % NCP;
            const int frow = tid / NCP;
            float2 sum = s.part[0][frow][fcp];
#pragma unroll
            for (int c = 1; c < NCHK; c++) {
                float2 p = s.part[c][frow][fcp];
                sum.x += p.x; sum.y += p.y;
            }
            const int xi = s.xi[frow][t];
            const float2 xw = *reinterpret_cast<const float2*>(&s.e2[xi * HIDN + 2 * fcp]);
            float h0 = tanhf(sum.x + xw.x);
            float h1 = tanhf(sum.y + xw.y);
            reinterpret_cast<float2*>(&s.hdup[2 * fcp])[frow]     = make_float2(h0, h0);
            reinterpret_cast<float2*>(&s.hdup[2 * fcp + 1])[frow] = make_float2(h1, h1);
        } else if (tid >= 256 && tid < 256 + 2 * VOCABN && t > 0) {
            // Phase 2b: finalize + store logits for step t-1
            const int k = tid - 256;
            const int v = k % VOCABN, row = k / VOCABN;
            float lg = 0.f;
#pragma unroll
            for (int c = 0; c < NCHK; c++) lg += s.lp[c][row][v];
            out_logits[(size_t)(b0 + row) * SEQN * VOCABN + (size_t)(t - 1) * VOCABN + v] = lg;
        }
        __syncthreads();
    }

    // ---- final hidden = h_{SEQ-1} ----
    if (write_h && tid < 2 * HIDN) {
        const int row = tid / HIDN, j = tid % HIDN;
        const float* base = reinterpret_cast<const float*>(&s.hdup[j]);
        out_hidden[(size_t)(b0 + row) * HIDN + j] = base[row * 2];
    }
}

// ---------------------------------------------------------------------------
// Launch
// ---------------------------------------------------------------------------
extern "C" void kernel_launch(void* const* d_in, const int* in_sizes, int n_in,
                              void* d_out, int out_size) {
    const void*  x      = d_in[0];                 // int64 (or demoted int32)
    const float* hidden = (const float*)d_in[1];
    const float* emb    = (const float*)d_in[2];
    const float* We     = (const float*)d_in[3];
    const float* Wh     = (const float*)d_in[4];
    const float* Wo     = (const float*)d_in[5];

    float* logits = (float*)d_out;
    const long long LOGITS_ELEMS = (long long)BATCHN * SEQN * VOCABN;
    int write_h = (out_size >= (int)(LOGITS_ELEMS + BATCHN * HIDN));
    float* outh = logits + LOGITS_ELEMS;

    prep_kernel<<<VOCABN, HIDN>>>(emb, We, (const int*)x);

    cudaFuncSetAttribute((const void*)scan_kernel,
                         cudaFuncAttributeMaxDynamicSharedMemorySize,
                         (int)sizeof(Smem));
    scan_kernel<<<BATCHN / 2, TPB, sizeof(Smem)>>>(
        x, hidden, Wh, Wo, logits, outh, write_h);
}